// round 5
// baseline (speedup 1.0000x reference)
#include <cuda_runtime.h>

#define NB 16            // batch
#define NS 65            // segments per batch
#define NR 1040          // NB*NS rows
#define NW 256           // candidate positions per row
#define ND 128           // feature dim
#define T_PAD 2176       // padded time length of x
#define LSEQ 2048        // MAX_LEN_SEQ
#define MIN_SEG 32
#define NOUT (NB * LSEQ) // 32768 output rows
#define SENT 0xFFFFFFFFu
#define FULL 0xffffffffu

__device__ int g_rowstart[NR + 1];
__device__ int g_offset[NR];
__device__ int g_L[1];

// Exact-boundary row count: smallest w in [0,NW] with floor(rn(w/sc)) >= Tm.
// w* lies within +-3 of Tm*sc, so probe an 8-wide window with INDEPENDENT
// IEEE divides using the reference's exact predicate.
__device__ __forceinline__ int row_count(int Tm, float sc) {
    if (Tm <= 0) return 0;
    float wr = (float)Tm * sc;
    int wlo = (int)wr - 3;
    if (wlo < 0) wlo = 0;
    if (wlo >= NW) return NW;
    float fT = (float)Tm;
    int cnt = NW;
    #pragma unroll
    for (int j = 0; j < 8; j++) {
        int w = wlo + j;
        bool fail = (w < NW) &&
                    (floorf(__fdiv_rn((float)w, sc)) >= fT);
        if (fail && w < cnt) cnt = w;   // ascending probes -> min = first fail
    }
    return cnt;
}

// ---------------------------------------------------------------------------
// Setup: per-batch segment-offset warp-scans, per-row count (window probe),
// block exclusive scan via shfl. Single block, 1024 threads, 2 barriers-ish.
// ---------------------------------------------------------------------------
__global__ void __launch_bounds__(1024)
setup_kernel(const float* __restrict__ scales,
             const int* __restrict__ len_seq,
             const int* __restrict__ len_seg_raw) {
    __shared__ int sh_seg[NR];
    __shared__ int sh_off[NR];
    __shared__ int sh_ws[32];
    int tid  = threadIdx.x;
    int wid  = tid >> 5;
    int lane = tid & 31;

    for (int i = tid; i < NR; i += 1024) sh_seg[i] = len_seg_raw[i] + MIN_SEG;
    __syncthreads();

    // per-batch exclusive cumsum: warp wb scans batch wb (65 elems, 3 chunks)
    if (wid < NB) {
        int base = wid * NS;
        int carry = 0;
        #pragma unroll
        for (int c = 0; c < 3; c++) {
            int i = c * 32 + lane;
            int v = (i < NS) ? sh_seg[base + i] : 0;
            int s = v;
            #pragma unroll
            for (int o = 1; o < 32; o <<= 1) {
                int u = __shfl_up_sync(FULL, s, o);
                if (lane >= o) s += u;
            }
            if (i < NS) sh_off[base + i] = carry + s - v;   // exclusive
            carry += __shfl_sync(FULL, s, 31);
        }
    }
    __syncthreads();

    // counts for rows 2*tid, 2*tid+1 (threads 0..519 active)
    int a0 = 0, a1 = 0;
    int i0 = 2 * tid, i1 = 2 * tid + 1;
    if (i0 < NR) {
        int b = i0 / NS;
        a0 = row_count(min(sh_seg[i0] - 1, len_seq[b] - 1 - sh_off[i0]),
                       scales[i0] + 0.5f);
    }
    if (i1 < NR) {
        int b = i1 / NS;
        a1 = row_count(min(sh_seg[i1] - 1, len_seq[b] - 1 - sh_off[i1]),
                       scales[i1] + 0.5f);
    }

    // block exclusive scan of s = a0+a1 via warp shfl + warp-sum pass
    int s = a0 + a1;
    int incl = s;
    #pragma unroll
    for (int o = 1; o < 32; o <<= 1) {
        int u = __shfl_up_sync(FULL, incl, o);
        if (lane >= o) incl += u;
    }
    if (lane == 31) sh_ws[wid] = incl;
    __syncthreads();
    if (wid == 0) {
        int ws = sh_ws[lane];
        #pragma unroll
        for (int o = 1; o < 32; o <<= 1) {
            int u = __shfl_up_sync(FULL, ws, o);
            if (lane >= o) ws += u;
        }
        sh_ws[lane] = ws;                 // inclusive warp sums
    }
    __syncthreads();
    int warp_base = (wid > 0) ? sh_ws[wid - 1] : 0;
    incl += warp_base;
    int excl = incl - s;

    if (i0 < NR) { g_rowstart[i0] = excl;      g_offset[i0] = sh_off[i0]; }
    if (i1 < NR) { g_rowstart[i1] = excl + a0; g_offset[i1] = sh_off[i1]; }
    if (tid == 519) {                      // holds rows 1038,1039 -> incl = total
        g_rowstart[NR] = incl;
        g_L[0] = incl / NB;
    }
}

// ---------------------------------------------------------------------------
// Gather: 2048 blocks x 256 threads; block covers 16 consecutive output rows
// of one batch. Warp 0 lanes 0-15 binary-search rowstart (L1-resident) and
// build descriptors in shared; then 8 warps lerp 2 rows each.
// ---------------------------------------------------------------------------
__global__ void __launch_bounds__(256)
gather_kernel(const float* __restrict__ x,
              const float* __restrict__ scales,
              float* __restrict__ out) {
#if __CUDA_ARCH__ >= 900
    cudaGridDependencySynchronize();   // PDL: wait for setup results
#endif
    __shared__ uint2 sd[16];
    int blk  = blockIdx.x;
    int b    = blk >> 7;               // 128 blocks per batch
    int t0   = (blk & 127) << 4;
    int tid  = threadIdx.x;
    int wib  = tid >> 5;
    int lane = tid & 31;
    int L    = g_L[0];

    if (wib == 0 && lane < 16) {
        int t = t0 + lane;
        uint2 e; e.x = SENT; e.y = 0;
        if (t < L) {
            int g = b * L + t;
            int lo = 0, hi = NR;       // rowstart[lo] <= g < rowstart[lo+1]
            while (hi - lo > 1) {
                int mid = (lo + hi) >> 1;
                if (g_rowstart[mid] <= g) lo = mid; else hi = mid;
            }
            int w    = g - g_rowstart[lo];
            int base = (lo / NS) * T_PAD + g_offset[lo];
            e.x = (unsigned)base | ((unsigned)w << 16);
            e.y = __float_as_uint(scales[lo] + 0.5f);
        }
        sd[lane] = e;
    }
    __syncthreads();

    uint2 e0 = sd[2 * wib];
    uint2 e1 = sd[2 * wib + 1];
    bool v0 = (e0.x != SENT);
    bool v1 = (e1.x != SENT);

    float4 a0, c0, a1, c1;
    float lam0 = 0.f, lam1 = 0.f;
    if (v0) {
        int base = (int)(e0.x & 0xFFFFu), w = (int)(e0.x >> 16);
        float fs = __fdiv_rn((float)w, __uint_as_float(e0.y));
        float fl = floorf(fs); lam0 = fs - fl;
        const float4* p = (const float4*)(x + (size_t)(base + (int)fl) * ND);
        a0 = p[lane]; c0 = p[lane + 32];
    }
    if (v1) {
        int base = (int)(e1.x & 0xFFFFu), w = (int)(e1.x >> 16);
        float fs = __fdiv_rn((float)w, __uint_as_float(e1.y));
        float fl = floorf(fs); lam1 = fs - fl;
        const float4* p = (const float4*)(x + (size_t)(base + (int)fl) * ND);
        a1 = p[lane]; c1 = p[lane + 32];
    }

    float4 y0 = make_float4(0.f, 0.f, 0.f, 0.f);
    float4 y1 = y0;
    if (v0) {
        float om = 1.0f - lam0;
        y0.x = om * a0.x + lam0 * c0.x;  y0.y = om * a0.y + lam0 * c0.y;
        y0.z = om * a0.z + lam0 * c0.z;  y0.w = om * a0.w + lam0 * c0.w;
    }
    if (v1) {
        float om = 1.0f - lam1;
        y1.x = om * a1.x + lam1 * c1.x;  y1.y = om * a1.y + lam1 * c1.y;
        y1.z = om * a1.z + lam1 * c1.z;  y1.w = om * a1.w + lam1 * c1.w;
    }
    int gid0 = blk * 16 + 2 * wib;
    ((float4*)(out + (size_t)gid0 * ND))[lane]       = y0;
    ((float4*)(out + (size_t)(gid0 + 1) * ND))[lane] = y1;
}

extern "C" void kernel_launch(void* const* d_in, const int* in_sizes, int n_in,
                              void* d_out, int out_size) {
    const float* x           = (const float*)d_in[0];
    const float* scales      = (const float*)d_in[1];
    const int*   len_seq     = (const int*)d_in[2];
    const int*   len_seg_raw = (const int*)d_in[3];
    float* out = (float*)d_out;

    setup_kernel<<<1, 1024>>>(scales, len_seq, len_seg_raw);

    cudaLaunchConfig_t cfg = {};
    cfg.gridDim  = dim3(NOUT / 16);    // 2048 blocks
    cfg.blockDim = dim3(256);
    cfg.dynamicSmemBytes = 0;
    cfg.stream = 0;
    cudaLaunchAttribute attr[1];
    attr[0].id = cudaLaunchAttributeProgrammaticStreamSerialization;
    attr[0].val.programmaticStreamSerializationAllowed = 1;
    cfg.attrs = attr;
    cfg.numAttrs = 1;
    void* args[] = { (void*)&x, (void*)&scales, (void*)&out };
    cudaLaunchKernelExC(&cfg, (void*)gather_kernel, args);
}

// round 6
// speedup vs baseline: 1.0605x; 1.0605x over previous
#include <cuda_runtime.h>

#define NB 16            // batch
#define NS 65            // segments per batch
#define NR 1040          // NB*NS rows
#define NW 256           // candidate positions per row
#define ND 128           // feature dim
#define T_PAD 2176       // padded time length of x
#define LSEQ 2048        // MAX_LEN_SEQ
#define MIN_SEG 32
#define NOUT (NB * LSEQ) // 32768 output rows
#define SENT 0xFFFFFFFFu
#define FULL 0xffffffffu

#define EXP_BLOCKS 130
#define FILL_BLOCKS 30

__device__ int  g_rowstart[NR + 1];
__device__ int  g_offset[NR];
__device__ int  g_L[1];
__device__ uint2 g_entry[NOUT];   // .x = base|(w<<16), .y = scale bits; SENT = zero row

// Exact-boundary row count: smallest w in [0,NW] with floor(rn(w/sc)) >= Tm.
// w* lies within +-3 of Tm*sc, so probe an 8-wide window with INDEPENDENT
// IEEE divides using the reference's exact predicate.
__device__ __forceinline__ int row_count(int Tm, float sc) {
    if (Tm <= 0) return 0;
    float wr = (float)Tm * sc;
    int wlo = (int)wr - 3;
    if (wlo < 0) wlo = 0;
    if (wlo >= NW) return NW;
    float fT = (float)Tm;
    int cnt = NW;
    #pragma unroll
    for (int j = 0; j < 8; j++) {
        int w = wlo + j;
        bool fail = (w < NW) && (floorf(__fdiv_rn((float)w, sc)) >= fT);
        if (fail && w < cnt) cnt = w;   // ascending -> min = first fail
    }
    return cnt;
}

// ---------------------------------------------------------------------------
// Setup: per-batch segment-offset warp-scans, per-row count (window probe),
// block exclusive scan via shfl. Single block, 1024 threads.
// ---------------------------------------------------------------------------
__global__ void __launch_bounds__(1024)
setup_kernel(const float* __restrict__ scales,
             const int* __restrict__ len_seq,
             const int* __restrict__ len_seg_raw) {
    __shared__ int sh_seg[NR];
    __shared__ int sh_off[NR];
    __shared__ int sh_ws[32];
    int tid  = threadIdx.x;
    int wid  = tid >> 5;
    int lane = tid & 31;

    for (int i = tid; i < NR; i += 1024) sh_seg[i] = len_seg_raw[i] + MIN_SEG;
    __syncthreads();

    if (wid < NB) {      // warp wb scans batch wb (65 elems, 3 chunks)
        int base = wid * NS;
        int carry = 0;
        #pragma unroll
        for (int c = 0; c < 3; c++) {
            int i = c * 32 + lane;
            int v = (i < NS) ? sh_seg[base + i] : 0;
            int s = v;
            #pragma unroll
            for (int o = 1; o < 32; o <<= 1) {
                int u = __shfl_up_sync(FULL, s, o);
                if (lane >= o) s += u;
            }
            if (i < NS) sh_off[base + i] = carry + s - v;   // exclusive
            carry += __shfl_sync(FULL, s, 31);
        }
    }
    __syncthreads();

    int a0 = 0, a1 = 0;
    int i0 = 2 * tid, i1 = 2 * tid + 1;
    if (i0 < NR) {
        int b = i0 / NS;
        a0 = row_count(min(sh_seg[i0] - 1, len_seq[b] - 1 - sh_off[i0]),
                       scales[i0] + 0.5f);
    }
    if (i1 < NR) {
        int b = i1 / NS;
        a1 = row_count(min(sh_seg[i1] - 1, len_seq[b] - 1 - sh_off[i1]),
                       scales[i1] + 0.5f);
    }

    int s = a0 + a1;
    int incl = s;
    #pragma unroll
    for (int o = 1; o < 32; o <<= 1) {
        int u = __shfl_up_sync(FULL, incl, o);
        if (lane >= o) incl += u;
    }
    if (lane == 31) sh_ws[wid] = incl;
    __syncthreads();
    if (wid == 0) {
        int ws = sh_ws[lane];
        #pragma unroll
        for (int o = 1; o < 32; o <<= 1) {
            int u = __shfl_up_sync(FULL, ws, o);
            if (lane >= o) ws += u;
        }
        sh_ws[lane] = ws;
    }
    __syncthreads();
    int warp_base = (wid > 0) ? sh_ws[wid - 1] : 0;
    incl += warp_base;
    int excl = incl - s;

    if (i0 < NR) { g_rowstart[i0] = excl;      g_offset[i0] = sh_off[i0]; }
    if (i1 < NR) { g_rowstart[i1] = excl + a0; g_offset[i1] = sh_off[i1]; }
    if (tid == 519) {                   // rows 1038,1039 -> incl = total
        g_rowstart[NR] = incl;
        g_L[0] = incl / NB;
    }
}

// ---------------------------------------------------------------------------
// Expand: grid-wide table build. Blocks [0,130): warp-per-segment-row run
// expansion. Blocks [130,160): sentinel fill for t >= L (disjoint entries).
// ---------------------------------------------------------------------------
__global__ void __launch_bounds__(256)
expand_kernel(const float* __restrict__ scales) {
#if __CUDA_ARCH__ >= 900
    cudaGridDependencySynchronize();
#endif
    int L = g_L[0];
    if (blockIdx.x < EXP_BLOCKS) {
        int r = (blockIdx.x * 256 + threadIdx.x) >> 5;
        int lane = threadIdx.x & 31;
        if (r >= NR) return;
        int g0  = g_rowstart[r];
        int cnt = g_rowstart[r + 1] - g0;
        if (cnt == 0) return;
        int base = (r / NS) * T_PAD + g_offset[r];
        uint2 ev;
        ev.y = __float_as_uint(scales[r] + 0.5f);
        for (int k = lane; k < cnt; k += 32) {
            int g  = g0 + k;
            int bo = g / L;
            int t  = g - bo * L;
            if (bo < NB && t < LSEQ) {
                ev.x = (unsigned)base | ((unsigned)k << 16);
                g_entry[bo * LSEQ + t] = ev;
            }
        }
    } else {
        uint2 sent; sent.x = SENT; sent.y = 0;
        int i0 = (blockIdx.x - EXP_BLOCKS) * 256 + threadIdx.x;
        for (int i = i0; i < NOUT; i += FILL_BLOCKS * 256) {
            int t = i & (LSEQ - 1);
            if (t >= L) g_entry[i] = sent;
        }
    }
}

// ---------------------------------------------------------------------------
// Gather: two output rows per warp; descriptors via one 16B load; four
// independent 512B row loads in flight; streaming stores (out never re-read).
// ---------------------------------------------------------------------------
__global__ void __launch_bounds__(256)
gather_kernel(const float* __restrict__ x, float* __restrict__ out) {
#if __CUDA_ARCH__ >= 900
    cudaGridDependencySynchronize();
#endif
    int warp = (blockIdx.x * blockDim.x + threadIdx.x) >> 5;
    int lane = threadIdx.x & 31;
    int gid0 = warp << 1;
    if (gid0 >= NOUT) return;

    uint4 ee = __ldg((const uint4*)(g_entry + gid0));
    bool v0 = (ee.x != SENT);
    bool v1 = (ee.z != SENT);

    float4 a0, c0, a1, c1;
    float lam0 = 0.f, lam1 = 0.f;
    if (v0) {
        int base = (int)(ee.x & 0xFFFFu), w = (int)(ee.x >> 16);
        float fs = __fdiv_rn((float)w, __uint_as_float(ee.y));
        float fl = floorf(fs); lam0 = fs - fl;
        const float4* p = (const float4*)(x + (size_t)(base + (int)fl) * ND);
        a0 = p[lane]; c0 = p[lane + 32];
    }
    if (v1) {
        int base = (int)(ee.z & 0xFFFFu), w = (int)(ee.z >> 16);
        float fs = __fdiv_rn((float)w, __uint_as_float(ee.w));
        float fl = floorf(fs); lam1 = fs - fl;
        const float4* p = (const float4*)(x + (size_t)(base + (int)fl) * ND);
        a1 = p[lane]; c1 = p[lane + 32];
    }

    float4 y0 = make_float4(0.f, 0.f, 0.f, 0.f);
    float4 y1 = y0;
    if (v0) {
        float om = 1.0f - lam0;
        y0.x = om * a0.x + lam0 * c0.x;  y0.y = om * a0.y + lam0 * c0.y;
        y0.z = om * a0.z + lam0 * c0.z;  y0.w = om * a0.w + lam0 * c0.w;
    }
    if (v1) {
        float om = 1.0f - lam1;
        y1.x = om * a1.x + lam1 * c1.x;  y1.y = om * a1.y + lam1 * c1.y;
        y1.z = om * a1.z + lam1 * c1.z;  y1.w = om * a1.w + lam1 * c1.w;
    }
    __stcs((float4*)(out + (size_t)gid0 * ND) + lane,       y0);
    __stcs((float4*)(out + (size_t)(gid0 + 1) * ND) + lane, y1);
}

static inline void launch_pdl(void* fn, dim3 grid, dim3 block, void** args) {
    cudaLaunchConfig_t cfg = {};
    cfg.gridDim = grid;
    cfg.blockDim = block;
    cfg.dynamicSmemBytes = 0;
    cfg.stream = 0;
    cudaLaunchAttribute attr[1];
    attr[0].id = cudaLaunchAttributeProgrammaticStreamSerialization;
    attr[0].val.programmaticStreamSerializationAllowed = 1;
    cfg.attrs = attr;
    cfg.numAttrs = 1;
    cudaLaunchKernelExC(&cfg, fn, args);
}

extern "C" void kernel_launch(void* const* d_in, const int* in_sizes, int n_in,
                              void* d_out, int out_size) {
    const float* x           = (const float*)d_in[0];
    const float* scales      = (const float*)d_in[1];
    const int*   len_seq     = (const int*)d_in[2];
    const int*   len_seg_raw = (const int*)d_in[3];
    float* out = (float*)d_out;

    setup_kernel<<<1, 1024>>>(scales, len_seq, len_seg_raw);

    {
        void* args[] = { (void*)&scales };
        launch_pdl((void*)expand_kernel,
                   dim3(EXP_BLOCKS + FILL_BLOCKS), dim3(256), args);
    }
    {
        void* args[] = { (void*)&x, (void*)&out };
        launch_pdl((void*)gather_kernel, dim3(NOUT / 2 / 8), dim3(256), args);
    }
}